// round 3
// baseline (speedup 1.0000x reference)
#include <cuda_runtime.h>

#define NN 50000
#define EE 800000
#define IND 16
#define H 64
#define EAD 8
#define KM (2*H + EAD)   // 136

// Scratch state (no cudaMalloc allowed)
__device__ float g_h[NN * H];     // node hidden state [N,64]
__device__ float g_agg[NN * H];   // per-round aggregation buffer [N,64]

// ---------------------------------------------------------------------------
// Encoder: h = x @ W_enc + b_enc   ([N,16] @ [16,64])
// ---------------------------------------------------------------------------
__global__ void enc_kernel(const float* __restrict__ x,
                           const float* __restrict__ W,
                           const float* __restrict__ b) {
    __shared__ float Ws[IND * H];
    __shared__ float bs[H];
    for (int i = threadIdx.x; i < IND * H; i += blockDim.x) Ws[i] = W[i];
    if (threadIdx.x < H) bs[threadIdx.x] = b[threadIdx.x];
    __syncthreads();
    int node = blockIdx.x * blockDim.x + threadIdx.x;
    if (node >= NN) return;
    float xv[IND];
#pragma unroll
    for (int k = 0; k < IND; k++) xv[k] = x[node * IND + k];
#pragma unroll 4
    for (int n = 0; n < H; n++) {
        float acc = bs[n];
#pragma unroll
        for (int k = 0; k < IND; k++) acc += xv[k] * Ws[k * H + n];
        g_h[node * H + n] = acc;
    }
}

__global__ void zero_agg_kernel() {
    int i = blockIdx.x * blockDim.x + threadIdx.x;
    if (i < NN * H) g_agg[i] = 0.f;
}

// ---------------------------------------------------------------------------
// Message + scatter-add:  m = relu([h_src | h_dst | ea] @ W_msg + b);
//                         agg[dst] += m   (atomic)
// Tile: 64 edges x 64 outputs, K=136. 256 threads, 4x4 register microtile.
// ---------------------------------------------------------------------------
__global__ void __launch_bounds__(256)
msg_kernel(const int* __restrict__ ei,
           const float* __restrict__ ea,
           const float* __restrict__ W,
           const float* __restrict__ b) {
    extern __shared__ float sm[];
    float* As = sm;               // [64][136] row-major
    float* Ws = sm + 64 * KM;     // [136][64] row-major
    const int* src = ei;
    const int* dst = ei + EE;
    int ebase = blockIdx.x * 64;

    for (int i = threadIdx.x; i < KM * H; i += 256) Ws[i] = W[i];
    for (int i = threadIdx.x; i < 64 * KM; i += 256) {
        int e = i / KM, k = i - e * KM;
        int ge = ebase + e;
        float v;
        if (k < H)            v = g_h[src[ge] * H + k];
        else if (k < 2 * H)   v = g_h[dst[ge] * H + (k - H)];
        else                  v = ea[ge * EAD + (k - 2 * H)];
        As[i] = v;
    }
    __syncthreads();

    int tn = threadIdx.x & 15, te = threadIdx.x >> 4;
    float acc[4][4] = {};
    for (int k = 0; k < KM; k += 4) {
        float4 av4[4];
#pragma unroll
        for (int i = 0; i < 4; i++)
            av4[i] = *(const float4*)(As + (te * 4 + i) * KM + k);
        const float* av = (const float*)av4;
#pragma unroll
        for (int kk = 0; kk < 4; kk++) {
            float4 w = *(const float4*)(Ws + (k + kk) * H + tn * 4);
#pragma unroll
            for (int i = 0; i < 4; i++) {
                float a = av[i * 4 + kk];
                acc[i][0] += a * w.x;
                acc[i][1] += a * w.y;
                acc[i][2] += a * w.z;
                acc[i][3] += a * w.w;
            }
        }
    }

    float4 bv = *(const float4*)(b + tn * 4);
#pragma unroll
    for (int i = 0; i < 4; i++) {
        int ge = ebase + te * 4 + i;
        int d = dst[ge];
        float* o = g_agg + d * H + tn * 4;
        atomicAdd(o + 0, fmaxf(acc[i][0] + bv.x, 0.f));
        atomicAdd(o + 1, fmaxf(acc[i][1] + bv.y, 0.f));
        atomicAdd(o + 2, fmaxf(acc[i][2] + bv.z, 0.f));
        atomicAdd(o + 3, fmaxf(acc[i][3] + bv.w, 0.f));
    }
}

// ---------------------------------------------------------------------------
// Update: h = relu([h | agg] @ W_upd + b)    (in-place per node)
// Tile: 64 nodes x 64 outputs, K=128.
// ---------------------------------------------------------------------------
__global__ void __launch_bounds__(256)
upd_kernel(const float* __restrict__ W, const float* __restrict__ b) {
    extern __shared__ float sm[];
    float* As = sm;               // [64][128]
    float* Ws = sm + 64 * 128;    // [128][64]
    int nbase = blockIdx.x * 64;

    for (int i = threadIdx.x; i < 128 * H; i += 256) Ws[i] = W[i];
    for (int i = threadIdx.x; i < 64 * 128; i += 256) {
        int nd = i >> 7, k = i & 127;
        int gn = nbase + nd;
        float v = 0.f;
        if (gn < NN) v = (k < H) ? g_h[gn * H + k] : g_agg[gn * H + (k - H)];
        As[i] = v;
    }
    __syncthreads();

    int tn = threadIdx.x & 15, te = threadIdx.x >> 4;
    float acc[4][4] = {};
    for (int k = 0; k < 128; k += 4) {
        float4 av4[4];
#pragma unroll
        for (int i = 0; i < 4; i++)
            av4[i] = *(const float4*)(As + (te * 4 + i) * 128 + k);
        const float* av = (const float*)av4;
#pragma unroll
        for (int kk = 0; kk < 4; kk++) {
            float4 w = *(const float4*)(Ws + (k + kk) * H + tn * 4);
#pragma unroll
            for (int i = 0; i < 4; i++) {
                float a = av[i * 4 + kk];
                acc[i][0] += a * w.x;
                acc[i][1] += a * w.y;
                acc[i][2] += a * w.z;
                acc[i][3] += a * w.w;
            }
        }
    }

    float4 bv = *(const float4*)(b + tn * 4);
#pragma unroll
    for (int i = 0; i < 4; i++) {
        int gn = nbase + te * 4 + i;
        if (gn < NN) {
            float4 r;
            r.x = fmaxf(acc[i][0] + bv.x, 0.f);
            r.y = fmaxf(acc[i][1] + bv.y, 0.f);
            r.z = fmaxf(acc[i][2] + bv.z, 0.f);
            r.w = fmaxf(acc[i][3] + bv.w, 0.f);
            *(float4*)(g_h + gn * H + tn * 4) = r;
        }
    }
}

// ---------------------------------------------------------------------------
// Node head: out = relu(h @ W1 + b1) @ W2 + b2    ([N,64]->[N,64]->[N,2])
// ---------------------------------------------------------------------------
__global__ void __launch_bounds__(256)
nodehead_kernel(const float* __restrict__ W1, const float* __restrict__ b1,
                const float* __restrict__ W2, const float* __restrict__ b2,
                float* __restrict__ out) {
    __shared__ float As[64 * 64];   // h tile, then reused as C1^T [n][nd]
    __shared__ float Ws[64 * 64];
    __shared__ float W2s[64 * 2];
    __shared__ float b2s[2];
    int nbase = blockIdx.x * 64;

    for (int i = threadIdx.x; i < 64 * 64; i += 256) Ws[i] = W1[i];
    if (threadIdx.x < 128) W2s[threadIdx.x] = W2[threadIdx.x];
    if (threadIdx.x < 2) b2s[threadIdx.x] = b2[threadIdx.x];
    for (int i = threadIdx.x; i < 64 * 64; i += 256) {
        int nd = i >> 6, k = i & 63;
        int gn = nbase + nd;
        As[i] = (gn < NN) ? g_h[gn * H + k] : 0.f;
    }
    __syncthreads();

    int tn = threadIdx.x & 15, te = threadIdx.x >> 4;
    float acc[4][4] = {};
    for (int k = 0; k < 64; k += 4) {
        float4 av4[4];
#pragma unroll
        for (int i = 0; i < 4; i++)
            av4[i] = *(const float4*)(As + (te * 4 + i) * 64 + k);
        const float* av = (const float*)av4;
#pragma unroll
        for (int kk = 0; kk < 4; kk++) {
            float4 w = *(const float4*)(Ws + (k + kk) * H + tn * 4);
#pragma unroll
            for (int i = 0; i < 4; i++) {
                float a = av[i * 4 + kk];
                acc[i][0] += a * w.x;
                acc[i][1] += a * w.y;
                acc[i][2] += a * w.z;
                acc[i][3] += a * w.w;
            }
        }
    }
    __syncthreads();

    float4 bv = *(const float4*)(b1 + tn * 4);
    const float* bvp = (const float*)&bv;
#pragma unroll
    for (int i = 0; i < 4; i++)
#pragma unroll
        for (int j = 0; j < 4; j++)
            As[(tn * 4 + j) * 64 + te * 4 + i] = fmaxf(acc[i][j] + bvp[j], 0.f);
    __syncthreads();

    if (threadIdx.x < 128) {
        int nd = threadIdx.x & 63, j = threadIdx.x >> 6;
        int gn = nbase + nd;
        if (gn < NN) {
            float s = b2s[j];
#pragma unroll 8
            for (int k = 0; k < 64; k++) s += As[k * 64 + nd] * W2s[k * 2 + j];
            out[gn * 2 + j] = s;
        }
    }
}

// ---------------------------------------------------------------------------
// Edge head (fully fused): e1=relu(F@W1+b1); e2=relu(e1@W2+b2); out=e2@W3+b3
// F = [h_src | h_dst | ea]  (K=136 -> 128 -> 64 -> 6), tile of 64 edges.
// ---------------------------------------------------------------------------
__global__ void __launch_bounds__(256)
edgehead_kernel(const int* __restrict__ ei, const float* __restrict__ ea,
                const float* __restrict__ W1, const float* __restrict__ b1,
                const float* __restrict__ W2, const float* __restrict__ b2,
                const float* __restrict__ W3, const float* __restrict__ b3,
                float* __restrict__ out) {
    extern __shared__ float sm[];
    float* bufA = sm;             // 8704 floats: F tile [64][136], then C1 [64][128]
    float* bufW = sm + 64 * KM;   // 17408 floats: W1 [136][128]; then W2 + C2^T + W3
    const int* src = ei;
    const int* dst = ei + EE;
    int ebase = blockIdx.x * 64;

    for (int i = threadIdx.x; i < KM * 128; i += 256) bufW[i] = W1[i];
    for (int i = threadIdx.x; i < 64 * KM; i += 256) {
        int e = i / KM, k = i - e * KM;
        int ge = ebase + e;
        float v;
        if (k < H)           v = g_h[src[ge] * H + k];
        else if (k < 2 * H)  v = g_h[dst[ge] * H + (k - H)];
        else                 v = ea[ge * EAD + (k - 2 * H)];
        bufA[i] = v;
    }
    __syncthreads();

    int tn = threadIdx.x & 15, te = threadIdx.x >> 4;

    // GEMM1: [64,136] @ [136,128] -> acc1[4e][8n]
    float acc1[4][8] = {};
    for (int k = 0; k < KM; k += 4) {
        float4 av4[4];
#pragma unroll
        for (int i = 0; i < 4; i++)
            av4[i] = *(const float4*)(bufA + (te * 4 + i) * KM + k);
        const float* av = (const float*)av4;
#pragma unroll
        for (int kk = 0; kk < 4; kk++) {
            float4 w0 = *(const float4*)(bufW + (k + kk) * 128 + tn * 8);
            float4 w1 = *(const float4*)(bufW + (k + kk) * 128 + tn * 8 + 4);
#pragma unroll
            for (int i = 0; i < 4; i++) {
                float a = av[i * 4 + kk];
                acc1[i][0] += a * w0.x; acc1[i][1] += a * w0.y;
                acc1[i][2] += a * w0.z; acc1[i][3] += a * w0.w;
                acc1[i][4] += a * w1.x; acc1[i][5] += a * w1.y;
                acc1[i][6] += a * w1.z; acc1[i][7] += a * w1.w;
            }
        }
    }
    __syncthreads();

    // epilogue1 -> C1 [e][128] in bufA ; load W2 into bufW
    {
        float4 ba = *(const float4*)(b1 + tn * 8);
        float4 bb = *(const float4*)(b1 + tn * 8 + 4);
        float bvv[8] = {ba.x, ba.y, ba.z, ba.w, bb.x, bb.y, bb.z, bb.w};
#pragma unroll
        for (int i = 0; i < 4; i++)
#pragma unroll
            for (int j = 0; j < 8; j++)
                bufA[(te * 4 + i) * 128 + tn * 8 + j] = fmaxf(acc1[i][j] + bvv[j], 0.f);
    }
    for (int i = threadIdx.x; i < 128 * 64; i += 256) bufW[i] = W2[i];
    __syncthreads();

    // GEMM2: [64,128] @ [128,64] -> acc2[4e][4n]
    float acc2[4][4] = {};
    for (int k = 0; k < 128; k += 4) {
        float4 av4[4];
#pragma unroll
        for (int i = 0; i < 4; i++)
            av4[i] = *(const float4*)(bufA + (te * 4 + i) * 128 + k);
        const float* av = (const float*)av4;
#pragma unroll
        for (int kk = 0; kk < 4; kk++) {
            float4 w = *(const float4*)(bufW + (k + kk) * H + tn * 4);
#pragma unroll
            for (int i = 0; i < 4; i++) {
                float a = av[i * 4 + kk];
                acc2[i][0] += a * w.x;
                acc2[i][1] += a * w.y;
                acc2[i][2] += a * w.z;
                acc2[i][3] += a * w.w;
            }
        }
    }
    __syncthreads();

    // epilogue2 -> C2^T [n][e] at bufW+8192 ; load W3/b3 at bufW+12288
    float* bufC = bufW + 128 * 64;      // 4096 floats
    float* W3s  = bufW + 12288;         // 384 floats
    float* b3s  = W3s + 384;            // 6 floats
    {
        float4 bv = *(const float4*)(b2 + tn * 4);
        const float* bvp = (const float*)&bv;
#pragma unroll
        for (int i = 0; i < 4; i++)
#pragma unroll
            for (int j = 0; j < 4; j++)
                bufC[(tn * 4 + j) * 64 + te * 4 + i] = fmaxf(acc2[i][j] + bvp[j], 0.f);
    }
    for (int i = threadIdx.x; i < 384; i += 256) W3s[i] = W3[i];   // FIX: strided (384 > 256 threads)
    if (threadIdx.x < 6) b3s[threadIdx.x] = b3[threadIdx.x];
    __syncthreads();

    // GEMM3: [64,64] @ [64,6] -> out   (FIX: strided over all 384 output lanes)
    for (int t = threadIdx.x; t < 384; t += 256) {
        int e = t & 63, j = t >> 6;
        float s = b3s[j];
#pragma unroll 8
        for (int k = 0; k < 64; k++) s += bufC[k * 64 + e] * W3s[k * 6 + j];
        out[(ebase + e) * 6 + j] = s;
    }
}

// ---------------------------------------------------------------------------

#define MSG_SMEM ((64 * KM + KM * 64) * 4)        // 69632
#define UPD_SMEM ((64 * 128 + 128 * 64) * 4)      // 65536
#define EH_SMEM  ((64 * KM + KM * 128) * 4)       // 104448

extern "C" void kernel_launch(void* const* d_in, const int* in_sizes, int n_in,
                              void* d_out, int out_size) {
    const float* x     = (const float*)d_in[0];
    const int*   ei    = (const int*)d_in[1];
    const float* ea    = (const float*)d_in[2];
    const float* W_enc = (const float*)d_in[3];
    const float* b_enc = (const float*)d_in[4];
    const float* W_msg = (const float*)d_in[5];
    const float* b_msg = (const float*)d_in[6];
    const float* W_upd = (const float*)d_in[7];
    const float* b_upd = (const float*)d_in[8];
    const float* W_nd1 = (const float*)d_in[9];
    const float* b_nd1 = (const float*)d_in[10];
    const float* W_nd2 = (const float*)d_in[11];
    const float* b_nd2 = (const float*)d_in[12];
    const float* W_ed1 = (const float*)d_in[13];
    const float* b_ed1 = (const float*)d_in[14];
    const float* W_ed2 = (const float*)d_in[15];
    const float* b_ed2 = (const float*)d_in[16];
    const float* W_ed3 = (const float*)d_in[17];
    const float* b_ed3 = (const float*)d_in[18];
    float* out = (float*)d_out;

    cudaFuncSetAttribute(msg_kernel, cudaFuncAttributeMaxDynamicSharedMemorySize, MSG_SMEM);
    cudaFuncSetAttribute(upd_kernel, cudaFuncAttributeMaxDynamicSharedMemorySize, UPD_SMEM);
    cudaFuncSetAttribute(edgehead_kernel, cudaFuncAttributeMaxDynamicSharedMemorySize, EH_SMEM);

    enc_kernel<<<(NN + 255) / 256, 256>>>(x, W_enc, b_enc);
    for (int l = 0; l < 3; l++) {
        zero_agg_kernel<<<(NN * H + 255) / 256, 256>>>();
        msg_kernel<<<EE / 64, 256, MSG_SMEM>>>(ei, ea, W_msg, b_msg);
        upd_kernel<<<(NN + 63) / 64, 256, UPD_SMEM>>>(W_upd, b_upd);
    }
    nodehead_kernel<<<(NN + 63) / 64, 256>>>(W_nd1, b_nd1, W_nd2, b_nd2, out);
    edgehead_kernel<<<EE / 64, 256, EH_SMEM>>>(ei, ea, W_ed1, b_ed1, W_ed2, b_ed2,
                                               W_ed3, b_ed3, out + 2 * NN);
}

// round 4
// speedup vs baseline: 1.1596x; 1.1596x over previous
#include <cuda_runtime.h>
#include <cstdint>

#define NN 50000
#define EE 800000
#define IND 16
#define H 64
#define EAD 8
#define KM (2*H + EAD)   // 136

// Scratch state (no cudaMalloc allowed)
__device__ float g_h[NN * H];     // node hidden state [N,64]
__device__ float g_agg[NN * H];   // per-round aggregation buffer [N,64]

// ---------------------------------------------------------------------------
// TF32 helpers (3xTF32 compensated MMA)
// ---------------------------------------------------------------------------
__device__ __forceinline__ uint32_t f2tf32(float a) {
    uint32_t r;
    asm("cvt.rna.tf32.f32 %0, %1;" : "=r"(r) : "f"(a));
    return r;
}
__device__ __forceinline__ void tf32split(float a, uint32_t& hi, uint32_t& lo) {
    hi = f2tf32(a);
    lo = f2tf32(a - __uint_as_float(hi));
}
__device__ __forceinline__ void mma_tf32(float* c, const uint32_t* a,
                                         uint32_t b0, uint32_t b1) {
    asm volatile(
        "mma.sync.aligned.m16n8k8.row.col.f32.tf32.tf32.f32 "
        "{%0,%1,%2,%3}, {%4,%5,%6,%7}, {%8,%9}, {%0,%1,%2,%3};"
        : "+f"(c[0]), "+f"(c[1]), "+f"(c[2]), "+f"(c[3])
        : "r"(a[0]), "r"(a[1]), "r"(a[2]), "r"(a[3]), "r"(b0), "r"(b1));
}

// ---------------------------------------------------------------------------
// Encoder: h = x @ W_enc + b_enc   ([N,16] @ [16,64])
// ---------------------------------------------------------------------------
__global__ void enc_kernel(const float* __restrict__ x,
                           const float* __restrict__ W,
                           const float* __restrict__ b) {
    __shared__ float Ws[IND * H];
    __shared__ float bs[H];
    for (int i = threadIdx.x; i < IND * H; i += blockDim.x) Ws[i] = W[i];
    if (threadIdx.x < H) bs[threadIdx.x] = b[threadIdx.x];
    __syncthreads();
    int node = blockIdx.x * blockDim.x + threadIdx.x;
    if (node >= NN) return;
    float xv[IND];
#pragma unroll
    for (int k = 0; k < IND; k++) xv[k] = x[node * IND + k];
#pragma unroll 4
    for (int n = 0; n < H; n++) {
        float acc = bs[n];
#pragma unroll
        for (int k = 0; k < IND; k++) acc += xv[k] * Ws[k * H + n];
        g_h[node * H + n] = acc;
    }
}

__global__ void zero_agg_kernel() {
    int i = blockIdx.x * blockDim.x + threadIdx.x;
    if (i < NN * H) g_agg[i] = 0.f;
}

// ---------------------------------------------------------------------------
// Message + scatter-add (TF32 MMA):
//   m = relu([h_src | h_dst | ea] @ W_msg + b);  agg[dst] += m
// Tile: 64 edges x 64 outs, K=136. 8 warps = 4(M) x 2(N); warp: 16x32.
// ---------------------------------------------------------------------------
#define AS_STR 140      // 12 mod 32 -> conflict-free A-frag loads
#define WS_STR 72       //  8 mod 32 -> conflict-free B-frag loads

__global__ void __launch_bounds__(256, 2)
msg_kernel(const int* __restrict__ ei,
           const float* __restrict__ ea,
           const float* __restrict__ W,
           const float* __restrict__ b) {
    extern __shared__ float sm[];
    float* As = sm;                    // [64][140]
    float* Ws = sm + 64 * AS_STR;      // [136][72]
    const int* src = ei;
    const int* dst = ei + EE;
    const int ebase = blockIdx.x * 64;
    const int tid = threadIdx.x;

    for (int i = tid; i < KM * H; i += 256) {
        int k = i >> 6, n = i & 63;
        Ws[k * WS_STR + n] = W[i];
    }
    for (int i = tid; i < 64 * KM; i += 256) {
        int e = i / KM, k = i - e * KM;
        int ge = ebase + e;
        float v;
        if (k < H)           v = g_h[src[ge] * H + k];
        else if (k < 2 * H)  v = g_h[dst[ge] * H + (k - H)];
        else                 v = ea[ge * EAD + (k - 2 * H)];
        As[e * AS_STR + k] = v;
    }
    __syncthreads();

    const int lane = tid & 31, warp = tid >> 5;
    const int g = lane >> 2, tig = lane & 3;
    const int warpM = warp & 3, warpN = warp >> 2;
    const int row0 = warpM * 16 + g;

    float acc[4][4] = {};
    for (int k0 = 0; k0 < KM; k0 += 8) {
        uint32_t ah[4], al[4];
        tf32split(As[ row0      * AS_STR + k0 + tig    ], ah[0], al[0]);
        tf32split(As[(row0 + 8) * AS_STR + k0 + tig    ], ah[1], al[1]);
        tf32split(As[ row0      * AS_STR + k0 + tig + 4], ah[2], al[2]);
        tf32split(As[(row0 + 8) * AS_STR + k0 + tig + 4], ah[3], al[3]);
#pragma unroll
        for (int nt = 0; nt < 4; nt++) {
            int n0 = warpN * 32 + nt * 8;
            uint32_t bh0, bl0, bh1, bl1;
            tf32split(Ws[(k0 + tig)     * WS_STR + n0 + g], bh0, bl0);
            tf32split(Ws[(k0 + tig + 4) * WS_STR + n0 + g], bh1, bl1);
            mma_tf32(acc[nt], ah, bh0, bh1);
            mma_tf32(acc[nt], ah, bl0, bl1);
            mma_tf32(acc[nt], al, bh0, bh1);
        }
    }

    // epilogue: relu(acc + bias) -> vector atomic scatter-add on dst
    const int d0 = dst[ebase + row0];
    const int d1 = dst[ebase + row0 + 8];
#pragma unroll
    for (int nt = 0; nt < 4; nt++) {
        int n = warpN * 32 + nt * 8 + 2 * tig;
        float bb0 = __ldg(b + n), bb1 = __ldg(b + n + 1);
        float2 v01 = make_float2(fmaxf(acc[nt][0] + bb0, 0.f),
                                 fmaxf(acc[nt][1] + bb1, 0.f));
        float2 v23 = make_float2(fmaxf(acc[nt][2] + bb0, 0.f),
                                 fmaxf(acc[nt][3] + bb1, 0.f));
        atomicAdd((float2*)(g_agg + d0 * H + n), v01);
        atomicAdd((float2*)(g_agg + d1 * H + n), v23);
    }
}

// ---------------------------------------------------------------------------
// Update: h = relu([h | agg] @ W_upd + b)    (FFMA; small fraction of runtime)
// ---------------------------------------------------------------------------
__global__ void __launch_bounds__(256)
upd_kernel(const float* __restrict__ W, const float* __restrict__ b) {
    extern __shared__ float sm[];
    float* As = sm;               // [64][128]
    float* Ws = sm + 64 * 128;    // [128][64]
    int nbase = blockIdx.x * 64;

    for (int i = threadIdx.x; i < 128 * H; i += 256) Ws[i] = W[i];
    for (int i = threadIdx.x; i < 64 * 128; i += 256) {
        int nd = i >> 7, k = i & 127;
        int gn = nbase + nd;
        float v = 0.f;
        if (gn < NN) v = (k < H) ? g_h[gn * H + k] : g_agg[gn * H + (k - H)];
        As[i] = v;
    }
    __syncthreads();

    int tn = threadIdx.x & 15, te = threadIdx.x >> 4;
    float acc[4][4] = {};
    for (int k = 0; k < 128; k += 4) {
        float4 av4[4];
#pragma unroll
        for (int i = 0; i < 4; i++)
            av4[i] = *(const float4*)(As + (te * 4 + i) * 128 + k);
        const float* av = (const float*)av4;
#pragma unroll
        for (int kk = 0; kk < 4; kk++) {
            float4 w = *(const float4*)(Ws + (k + kk) * H + tn * 4);
#pragma unroll
            for (int i = 0; i < 4; i++) {
                float a = av[i * 4 + kk];
                acc[i][0] += a * w.x;
                acc[i][1] += a * w.y;
                acc[i][2] += a * w.z;
                acc[i][3] += a * w.w;
            }
        }
    }

    float4 bv = *(const float4*)(b + tn * 4);
#pragma unroll
    for (int i = 0; i < 4; i++) {
        int gn = nbase + te * 4 + i;
        if (gn < NN) {
            float4 r;
            r.x = fmaxf(acc[i][0] + bv.x, 0.f);
            r.y = fmaxf(acc[i][1] + bv.y, 0.f);
            r.z = fmaxf(acc[i][2] + bv.z, 0.f);
            r.w = fmaxf(acc[i][3] + bv.w, 0.f);
            *(float4*)(g_h + gn * H + tn * 4) = r;
        }
    }
}

// ---------------------------------------------------------------------------
// Node head: out = relu(h @ W1 + b1) @ W2 + b2
// ---------------------------------------------------------------------------
__global__ void __launch_bounds__(256)
nodehead_kernel(const float* __restrict__ W1, const float* __restrict__ b1,
                const float* __restrict__ W2, const float* __restrict__ b2,
                float* __restrict__ out) {
    __shared__ float As[64 * 64];
    __shared__ float Ws[64 * 64];
    __shared__ float W2s[64 * 2];
    __shared__ float b2s[2];
    int nbase = blockIdx.x * 64;

    for (int i = threadIdx.x; i < 64 * 64; i += 256) Ws[i] = W1[i];
    if (threadIdx.x < 128) W2s[threadIdx.x] = W2[threadIdx.x];
    if (threadIdx.x < 2) b2s[threadIdx.x] = b2[threadIdx.x];
    for (int i = threadIdx.x; i < 64 * 64; i += 256) {
        int nd = i >> 6, k = i & 63;
        int gn = nbase + nd;
        As[i] = (gn < NN) ? g_h[gn * H + k] : 0.f;
    }
    __syncthreads();

    int tn = threadIdx.x & 15, te = threadIdx.x >> 4;
    float acc[4][4] = {};
    for (int k = 0; k < 64; k += 4) {
        float4 av4[4];
#pragma unroll
        for (int i = 0; i < 4; i++)
            av4[i] = *(const float4*)(As + (te * 4 + i) * 64 + k);
        const float* av = (const float*)av4;
#pragma unroll
        for (int kk = 0; kk < 4; kk++) {
            float4 w = *(const float4*)(Ws + (k + kk) * H + tn * 4);
#pragma unroll
            for (int i = 0; i < 4; i++) {
                float a = av[i * 4 + kk];
                acc[i][0] += a * w.x;
                acc[i][1] += a * w.y;
                acc[i][2] += a * w.z;
                acc[i][3] += a * w.w;
            }
        }
    }
    __syncthreads();

    float4 bv = *(const float4*)(b1 + tn * 4);
    const float* bvp = (const float*)&bv;
#pragma unroll
    for (int i = 0; i < 4; i++)
#pragma unroll
        for (int j = 0; j < 4; j++)
            As[(tn * 4 + j) * 64 + te * 4 + i] = fmaxf(acc[i][j] + bvp[j], 0.f);
    __syncthreads();

    if (threadIdx.x < 128) {
        int nd = threadIdx.x & 63, j = threadIdx.x >> 6;
        int gn = nbase + nd;
        if (gn < NN) {
            float s = b2s[j];
#pragma unroll 8
            for (int k = 0; k < 64; k++) s += As[k * 64 + nd] * W2s[k * 2 + j];
            out[gn * 2 + j] = s;
        }
    }
}

// ---------------------------------------------------------------------------
// Edge head (TF32 MMA, fully fused): 136 -> 128 -> 64 -> 6, tile 64 edges.
// ---------------------------------------------------------------------------
#define C1_STR 132      // 4 mod 32 -> conflict-free A-frag loads
#define W1_STR 136      // 8 mod 32
#define C2_STR 66

__global__ void __launch_bounds__(256)
edgehead_kernel(const int* __restrict__ ei, const float* __restrict__ ea,
                const float* __restrict__ W1, const float* __restrict__ b1,
                const float* __restrict__ W2, const float* __restrict__ b2,
                const float* __restrict__ W3, const float* __restrict__ b3,
                float* __restrict__ out) {
    extern __shared__ float sm[];
    float* bufA = sm;                  // 8960 floats: F [64][140]; later C1 [64][132]
    float* bufW = sm + 64 * AS_STR;    // 18496 floats: W1 [136][136]; later W2/C2/W3
    const int* src = ei;
    const int* dst = ei + EE;
    const int ebase = blockIdx.x * 64;
    const int tid = threadIdx.x;

    for (int i = tid; i < KM * 128; i += 256) {
        int k = i >> 7, n = i & 127;
        bufW[k * W1_STR + n] = W1[i];
    }
    for (int i = tid; i < 64 * KM; i += 256) {
        int e = i / KM, k = i - e * KM;
        int ge = ebase + e;
        float v;
        if (k < H)           v = g_h[src[ge] * H + k];
        else if (k < 2 * H)  v = g_h[dst[ge] * H + (k - H)];
        else                 v = ea[ge * EAD + (k - 2 * H)];
        bufA[e * AS_STR + k] = v;
    }
    __syncthreads();

    const int lane = tid & 31, warp = tid >> 5;
    const int g = lane >> 2, tig = lane & 3;
    const int warpM = warp & 3, warpN = warp >> 2;
    const int row0 = warpM * 16 + g;

    // GEMM1: [64,136] @ [136,128] ; warp tile 16 x 64 (8 n-tiles)
    float acc1[8][4] = {};
    for (int k0 = 0; k0 < KM; k0 += 8) {
        uint32_t ah[4], al[4];
        tf32split(bufA[ row0      * AS_STR + k0 + tig    ], ah[0], al[0]);
        tf32split(bufA[(row0 + 8) * AS_STR + k0 + tig    ], ah[1], al[1]);
        tf32split(bufA[ row0      * AS_STR + k0 + tig + 4], ah[2], al[2]);
        tf32split(bufA[(row0 + 8) * AS_STR + k0 + tig + 4], ah[3], al[3]);
#pragma unroll
        for (int nt = 0; nt < 8; nt++) {
            int n0 = warpN * 64 + nt * 8;
            uint32_t bh0, bl0, bh1, bl1;
            tf32split(bufW[(k0 + tig)     * W1_STR + n0 + g], bh0, bl0);
            tf32split(bufW[(k0 + tig + 4) * W1_STR + n0 + g], bh1, bl1);
            mma_tf32(acc1[nt], ah, bh0, bh1);
            mma_tf32(acc1[nt], ah, bl0, bl1);
            mma_tf32(acc1[nt], al, bh0, bh1);
        }
    }
    __syncthreads();   // all reads of F/W1 done

    // epilogue1: C1 = relu(acc1 + b1) -> bufA [64][132] ; load W2 -> bufW [128][72]
#pragma unroll
    for (int nt = 0; nt < 8; nt++) {
        int n = warpN * 64 + nt * 8 + 2 * tig;
        float bb0 = __ldg(b1 + n), bb1 = __ldg(b1 + n + 1);
        *(float2*)(bufA + row0 * C1_STR + n) =
            make_float2(fmaxf(acc1[nt][0] + bb0, 0.f), fmaxf(acc1[nt][1] + bb1, 0.f));
        *(float2*)(bufA + (row0 + 8) * C1_STR + n) =
            make_float2(fmaxf(acc1[nt][2] + bb0, 0.f), fmaxf(acc1[nt][3] + bb1, 0.f));
    }
    for (int i = tid; i < 128 * H; i += 256) {
        int k = i >> 6, n = i & 63;
        bufW[k * WS_STR + n] = W2[i];
    }
    __syncthreads();

    // GEMM2: [64,128] @ [128,64] ; warp tile 16 x 32 (4 n-tiles)
    float acc2[4][4] = {};
    for (int k0 = 0; k0 < 128; k0 += 8) {
        uint32_t ah[4], al[4];
        tf32split(bufA[ row0      * C1_STR + k0 + tig    ], ah[0], al[0]);
        tf32split(bufA[(row0 + 8) * C1_STR + k0 + tig    ], ah[1], al[1]);
        tf32split(bufA[ row0      * C1_STR + k0 + tig + 4], ah[2], al[2]);
        tf32split(bufA[(row0 + 8) * C1_STR + k0 + tig + 4], ah[3], al[3]);
#pragma unroll
        for (int nt = 0; nt < 4; nt++) {
            int n0 = warpN * 32 + nt * 8;
            uint32_t bh0, bl0, bh1, bl1;
            tf32split(bufW[(k0 + tig)     * WS_STR + n0 + g], bh0, bl0);
            tf32split(bufW[(k0 + tig + 4) * WS_STR + n0 + g], bh1, bl1);
            mma_tf32(acc2[nt], ah, bh0, bh1);
            mma_tf32(acc2[nt], ah, bl0, bl1);
            mma_tf32(acc2[nt], al, bh0, bh1);
        }
    }
    __syncthreads();   // all reads of C1/W2 done

    // epilogue2: C2 = relu(acc2 + b2) -> bufC [64][66] ; load W3/b3
    float* bufC = bufW + 128 * WS_STR;   // offset 9216 floats, 64*66=4224
    float* W3s  = bufW + 13600;          // 384 floats
    float* b3s  = W3s + 384;             // 6 floats
#pragma unroll
    for (int nt = 0; nt < 4; nt++) {
        int n = warpN * 32 + nt * 8 + 2 * tig;
        float bb0 = __ldg(b2 + n), bb1 = __ldg(b2 + n + 1);
        *(float2*)(bufC + row0 * C2_STR + n) =
            make_float2(fmaxf(acc2[nt][0] + bb0, 0.f), fmaxf(acc2[nt][1] + bb1, 0.f));
        *(float2*)(bufC + (row0 + 8) * C2_STR + n) =
            make_float2(fmaxf(acc2[nt][2] + bb0, 0.f), fmaxf(acc2[nt][3] + bb1, 0.f));
    }
    for (int i = tid; i < 384; i += 256) W3s[i] = W3[i];
    if (tid < 6) b3s[tid] = b3[tid];
    __syncthreads();

    // GEMM3: [64,64] @ [64,6] -> out
    for (int t = tid; t < 384; t += 256) {
        int e = t & 63, j = t >> 6;
        float s = b3s[j];
#pragma unroll 8
        for (int k = 0; k < 64; k++) s += bufC[e * C2_STR + k] * W3s[k * 6 + j];
        out[(ebase + e) * 6 + j] = s;
    }
}

// ---------------------------------------------------------------------------

#define MSG_SMEM ((64 * AS_STR + KM * WS_STR) * 4)    // 75008
#define UPD_SMEM ((64 * 128 + 128 * 64) * 4)          // 65536
#define EH_SMEM  ((64 * AS_STR + KM * W1_STR) * 4)    // 109824

extern "C" void kernel_launch(void* const* d_in, const int* in_sizes, int n_in,
                              void* d_out, int out_size) {
    const float* x     = (const float*)d_in[0];
    const int*   ei    = (const int*)d_in[1];
    const float* ea    = (const float*)d_in[2];
    const float* W_enc = (const float*)d_in[3];
    const float* b_enc = (const float*)d_in[4];
    const float* W_msg = (const float*)d_in[5];
    const float* b_msg = (const float*)d_in[6];
    const float* W_upd = (const float*)d_in[7];
    const float* b_upd = (const float*)d_in[8];
    const float* W_nd1 = (const float*)d_in[9];
    const float* b_nd1 = (const float*)d_in[10];
    const float* W_nd2 = (const float*)d_in[11];
    const float* b_nd2 = (const float*)d_in[12];
    const float* W_ed1 = (const float*)d_in[13];
    const float* b_ed1 = (const float*)d_in[14];
    const float* W_ed2 = (const float*)d_in[15];
    const float* b_ed2 = (const float*)d_in[16];
    const float* W_ed3 = (const float*)d_in[17];
    const float* b_ed3 = (const float*)d_in[18];
    float* out = (float*)d_out;

    cudaFuncSetAttribute(msg_kernel, cudaFuncAttributeMaxDynamicSharedMemorySize, MSG_SMEM);
    cudaFuncSetAttribute(upd_kernel, cudaFuncAttributeMaxDynamicSharedMemorySize, UPD_SMEM);
    cudaFuncSetAttribute(edgehead_kernel, cudaFuncAttributeMaxDynamicSharedMemorySize, EH_SMEM);

    enc_kernel<<<(NN + 255) / 256, 256>>>(x, W_enc, b_enc);
    for (int l = 0; l < 3; l++) {
        zero_agg_kernel<<<(NN * H + 255) / 256, 256>>>();
        msg_kernel<<<EE / 64, 256, MSG_SMEM>>>(ei, ea, W_msg, b_msg);
        upd_kernel<<<(NN + 63) / 64, 256, UPD_SMEM>>>(W_upd, b_upd);
    }
    nodehead_kernel<<<(NN + 63) / 64, 256>>>(W_nd1, b_nd1, W_nd2, b_nd2, out);
    edgehead_kernel<<<EE / 64, 256, EH_SMEM>>>(ei, ea, W_ed1, b_ed1, W_ed2, b_ed2,
                                               W_ed3, b_ed3, out + 2 * NN);
}

// round 5
// speedup vs baseline: 1.2762x; 1.1005x over previous
#include <cuda_runtime.h>
#include <cstdint>

#define NN 50000
#define EE 800000
#define IND 16
#define H 64
#define EAD 8
#define KM (2*H + EAD)   // 136

// Scratch state (no cudaMalloc allowed)
__device__ float g_h[NN * H];     // node hidden state [N,64]
__device__ float g_agg[NN * H];   // per-round aggregation buffer [N,64]

// Pre-split packed bf16x2 weights (hi/lo), laid out [k_pair][n] with smem strides
__device__ uint32_t g_Wmsg_h[72 * 72],  g_Wmsg_l[72 * 72];    // msg W: 68 pairs (K=136), n=64, STR=72
__device__ uint32_t g_Wupd_h[64 * 72],  g_Wupd_l[64 * 72];    // upd W: 64 pairs (K=128), n=64, STR=72
__device__ uint32_t g_We1_h[72 * 136],  g_We1_l[72 * 136];    // ed1 W: 68 pairs, n=128, STR=136
__device__ uint32_t g_We2_h[64 * 72],   g_We2_l[64 * 72];     // ed2 W: 64 pairs, n=64,  STR=72

// ---------------------------------------------------------------------------
// bf16 split helpers
// ---------------------------------------------------------------------------
__device__ __forceinline__ void splitpack(float a0, float a1, uint32_t& hi, uint32_t& lo) {
    uint32_t h, l;
    asm("cvt.rn.bf16x2.f32 %0, %1, %2;" : "=r"(h) : "f"(a1), "f"(a0));   // a0 -> low half
    float r0 = a0 - __uint_as_float(h << 16);
    float r1 = a1 - __uint_as_float(h & 0xFFFF0000u);
    asm("cvt.rn.bf16x2.f32 %0, %1, %2;" : "=r"(l) : "f"(r1), "f"(r0));
    hi = h; lo = l;
}

__device__ __forceinline__ void mma_bf16(float* c, const uint32_t* a, uint32_t b0, uint32_t b1) {
    asm volatile(
        "mma.sync.aligned.m16n8k16.row.col.f32.bf16.bf16.f32 "
        "{%0,%1,%2,%3}, {%4,%5,%6,%7}, {%8,%9}, {%0,%1,%2,%3};"
        : "+f"(c[0]), "+f"(c[1]), "+f"(c[2]), "+f"(c[3])
        : "r"(a[0]), "r"(a[1]), "r"(a[2]), "r"(a[3]), "r"(b0), "r"(b1));
}

// ---------------------------------------------------------------------------
// Setup: split all weight matrices into packed bf16x2 hi/lo, padded layouts.
// ---------------------------------------------------------------------------
__device__ __forceinline__ void split_one(const float* W, int K2, int N, int STR,
                                          uint32_t* oh, uint32_t* ol, int i) {
    int kp = i / STR, n = i - kp * STR;
    float a0 = 0.f, a1 = 0.f;
    if (n < N && kp < K2) { a0 = W[(2 * kp) * N + n]; a1 = W[(2 * kp + 1) * N + n]; }
    uint32_t h, l; splitpack(a0, a1, h, l);
    oh[i] = h; ol[i] = l;
}

#define SZ_MSG (72*72)
#define SZ_UPD (64*72)
#define SZ_E1  (72*136)
#define SZ_E2  (64*72)

__global__ void split_all_kernel(const float* __restrict__ Wm, const float* __restrict__ Wu,
                                 const float* __restrict__ W1, const float* __restrict__ W2) {
    int i = blockIdx.x * 256 + threadIdx.x;
    if (i < SZ_MSG) { split_one(Wm, 68, 64, 72, g_Wmsg_h, g_Wmsg_l, i); return; }
    i -= SZ_MSG;
    if (i < SZ_UPD) { split_one(Wu, 64, 64, 72, g_Wupd_h, g_Wupd_l, i); return; }
    i -= SZ_UPD;
    if (i < SZ_E1)  { split_one(W1, 68, 128, 136, g_We1_h, g_We1_l, i); return; }
    i -= SZ_E1;
    if (i < SZ_E2)  { split_one(W2, 64, 64, 72, g_We2_h, g_We2_l, i); return; }
}
#define SPLIT_TOTAL (SZ_MSG + SZ_UPD + SZ_E1 + SZ_E2)

// ---------------------------------------------------------------------------
// Encoder: h = x @ W_enc + b_enc   ([N,16] @ [16,64])
// ---------------------------------------------------------------------------
__global__ void enc_kernel(const float* __restrict__ x,
                           const float* __restrict__ W,
                           const float* __restrict__ b) {
    __shared__ float Ws[IND * H];
    __shared__ float bs[H];
    for (int i = threadIdx.x; i < IND * H; i += blockDim.x) Ws[i] = W[i];
    if (threadIdx.x < H) bs[threadIdx.x] = b[threadIdx.x];
    __syncthreads();
    int node = blockIdx.x * blockDim.x + threadIdx.x;
    if (node >= NN) return;
    float xv[IND];
#pragma unroll
    for (int k = 0; k < IND; k++) xv[k] = x[node * IND + k];
#pragma unroll 4
    for (int n = 0; n < H; n++) {
        float acc = bs[n];
#pragma unroll
        for (int k = 0; k < IND; k++) acc += xv[k] * Ws[k * H + n];
        g_h[node * H + n] = acc;
    }
}

__global__ void zero_agg_kernel() {
    int i = blockIdx.x * blockDim.x + threadIdx.x;
    if (i < NN * H) g_agg[i] = 0.f;
}

// ---------------------------------------------------------------------------
// Message + scatter-add (bf16x3 MMA):
//   m = relu([h_src | h_dst | ea] @ W_msg + b);  agg[dst] += m
// Tile 64 edges x 64 outs, K=136 (pad 144 = 72 pairs, 9 k16-steps).
// 8 warps = 4(M) x 2(N); warp tile 16x32.
// ---------------------------------------------------------------------------
#define STRA 76     // A pk stride (12 mod 32, conflict-free: g*12+tig distinct)
#define STRB 72     // B pk stride ( 8 mod 32, conflict-free: tig*8+g distinct)

#define MSG_SMEM ((2*64*STRA + 2*72*STRB) * 4)    // 80384 B

__global__ void __launch_bounds__(256, 2)
msg_kernel(const int* __restrict__ ei,
           const float* __restrict__ ea,
           const float* __restrict__ b) {
    extern __shared__ uint32_t sm32[];
    uint32_t* Ah = sm32;                 // [64][76]
    uint32_t* Al = Ah + 64 * STRA;
    uint32_t* Bh = Al + 64 * STRA;       // [72][72]
    uint32_t* Bl = Bh + 72 * STRB;
    const int* src = ei;
    const int* dst = ei + EE;
    const int ebase = blockIdx.x * 64;
    const int tid = threadIdx.x;

    for (int i = tid; i < 72 * STRB; i += 256) { Bh[i] = g_Wmsg_h[i]; Bl[i] = g_Wmsg_l[i]; }
    for (int i = tid; i < 64 * 72; i += 256) {
        int e = i / 72, kp = i - e * 72;
        int ge = ebase + e;
        float2 v;
        if (kp < 32)      v = *(const float2*)(g_h + src[ge] * H + 2 * kp);
        else if (kp < 64) v = *(const float2*)(g_h + dst[ge] * H + 2 * (kp - 32));
        else if (kp < 68) v = *(const float2*)(ea + ge * EAD + 2 * (kp - 64));
        else              v = make_float2(0.f, 0.f);
        splitpack(v.x, v.y, Ah[e * STRA + kp], Al[e * STRA + kp]);
    }
    __syncthreads();

    const int lane = tid & 31, warp = tid >> 5;
    const int g = lane >> 2, tig = lane & 3;
    const int warpM = warp & 3, warpN = warp >> 2;
    const int row0 = warpM * 16 + g;

    float acc[4][4] = {};
#pragma unroll
    for (int s = 0; s < 9; s++) {
        const int k0p = s * 8;
        uint32_t ah[4], al[4];
        ah[0] = Ah[ row0      * STRA + k0p + tig    ];
        ah[1] = Ah[(row0 + 8) * STRA + k0p + tig    ];
        ah[2] = Ah[ row0      * STRA + k0p + tig + 4];
        ah[3] = Ah[(row0 + 8) * STRA + k0p + tig + 4];
        al[0] = Al[ row0      * STRA + k0p + tig    ];
        al[1] = Al[(row0 + 8) * STRA + k0p + tig    ];
        al[2] = Al[ row0      * STRA + k0p + tig + 4];
        al[3] = Al[(row0 + 8) * STRA + k0p + tig + 4];
#pragma unroll
        for (int nt = 0; nt < 4; nt++) {
            int n = warpN * 32 + nt * 8 + g;
            uint32_t bh0 = Bh[(k0p + tig)     * STRB + n];
            uint32_t bh1 = Bh[(k0p + tig + 4) * STRB + n];
            uint32_t bl0 = Bl[(k0p + tig)     * STRB + n];
            uint32_t bl1 = Bl[(k0p + tig + 4) * STRB + n];
            mma_bf16(acc[nt], ah, bh0, bh1);
            mma_bf16(acc[nt], al, bh0, bh1);
            mma_bf16(acc[nt], ah, bl0, bl1);
        }
    }

    // epilogue: relu(acc + bias) -> vector atomic scatter-add on dst
    const int d0 = dst[ebase + row0];
    const int d1 = dst[ebase + row0 + 8];
#pragma unroll
    for (int nt = 0; nt < 4; nt++) {
        int n = warpN * 32 + nt * 8 + 2 * tig;
        float bb0 = __ldg(b + n), bb1 = __ldg(b + n + 1);
        float2 v01 = make_float2(fmaxf(acc[nt][0] + bb0, 0.f),
                                 fmaxf(acc[nt][1] + bb1, 0.f));
        float2 v23 = make_float2(fmaxf(acc[nt][2] + bb0, 0.f),
                                 fmaxf(acc[nt][3] + bb1, 0.f));
        atomicAdd((float2*)(g_agg + d0 * H + n), v01);
        atomicAdd((float2*)(g_agg + d1 * H + n), v23);
    }
}

// ---------------------------------------------------------------------------
// Update (bf16x3 MMA): h = relu([h | agg] @ W_upd + b)
// Tile 64 nodes x 64 outs, K=128 (64 pairs, 8 k16-steps).
// ---------------------------------------------------------------------------
#define UPD_SMEM ((2*64*STRA + 2*64*STRB) * 4)    // 75776 B

__global__ void __launch_bounds__(256, 2)
upd_kernel(const float* __restrict__ b) {
    extern __shared__ uint32_t sm32[];
    uint32_t* Ah = sm32;                 // [64][76]
    uint32_t* Al = Ah + 64 * STRA;
    uint32_t* Bh = Al + 64 * STRA;       // [64][72]
    uint32_t* Bl = Bh + 64 * STRB;
    const int nbase = blockIdx.x * 64;
    const int tid = threadIdx.x;

    for (int i = tid; i < 64 * STRB; i += 256) { Bh[i] = g_Wupd_h[i]; Bl[i] = g_Wupd_l[i]; }
    for (int i = tid; i < 64 * 64; i += 256) {
        int nd = i >> 6, kp = i & 63;
        int gn = nbase + nd;
        float2 v = make_float2(0.f, 0.f);
        if (gn < NN)
            v = (kp < 32) ? *(const float2*)(g_h + gn * H + 2 * kp)
                          : *(const float2*)(g_agg + gn * H + 2 * (kp - 32));
        splitpack(v.x, v.y, Ah[nd * STRA + kp], Al[nd * STRA + kp]);
    }
    __syncthreads();

    const int lane = tid & 31, warp = tid >> 5;
    const int g = lane >> 2, tig = lane & 3;
    const int warpM = warp & 3, warpN = warp >> 2;
    const int row0 = warpM * 16 + g;

    float acc[4][4] = {};
#pragma unroll
    for (int s = 0; s < 8; s++) {
        const int k0p = s * 8;
        uint32_t ah[4], al[4];
        ah[0] = Ah[ row0      * STRA + k0p + tig    ];
        ah[1] = Ah[(row0 + 8) * STRA + k0p + tig    ];
        ah[2] = Ah[ row0      * STRA + k0p + tig + 4];
        ah[3] = Ah[(row0 + 8) * STRA + k0p + tig + 4];
        al[0] = Al[ row0      * STRA + k0p + tig    ];
        al[1] = Al[(row0 + 8) * STRA + k0p + tig    ];
        al[2] = Al[ row0      * STRA + k0p + tig + 4];
        al[3] = Al[(row0 + 8) * STRA + k0p + tig + 4];
#pragma unroll
        for (int nt = 0; nt < 4; nt++) {
            int n = warpN * 32 + nt * 8 + g;
            uint32_t bh0 = Bh[(k0p + tig)     * STRB + n];
            uint32_t bh1 = Bh[(k0p + tig + 4) * STRB + n];
            uint32_t bl0 = Bl[(k0p + tig)     * STRB + n];
            uint32_t bl1 = Bl[(k0p + tig + 4) * STRB + n];
            mma_bf16(acc[nt], ah, bh0, bh1);
            mma_bf16(acc[nt], al, bh0, bh1);
            mma_bf16(acc[nt], ah, bl0, bl1);
        }
    }

    const int gn0 = nbase + row0, gn1 = nbase + row0 + 8;
#pragma unroll
    for (int nt = 0; nt < 4; nt++) {
        int n = warpN * 32 + nt * 8 + 2 * tig;
        float bb0 = __ldg(b + n), bb1 = __ldg(b + n + 1);
        if (gn0 < NN)
            *(float2*)(g_h + gn0 * H + n) = make_float2(fmaxf(acc[nt][0] + bb0, 0.f),
                                                        fmaxf(acc[nt][1] + bb1, 0.f));
        if (gn1 < NN)
            *(float2*)(g_h + gn1 * H + n) = make_float2(fmaxf(acc[nt][2] + bb0, 0.f),
                                                        fmaxf(acc[nt][3] + bb1, 0.f));
    }
}

// ---------------------------------------------------------------------------
// Node head (FFMA; ~50us total): out = relu(h @ W1 + b1) @ W2 + b2
// ---------------------------------------------------------------------------
__global__ void __launch_bounds__(256)
nodehead_kernel(const float* __restrict__ W1, const float* __restrict__ b1,
                const float* __restrict__ W2, const float* __restrict__ b2,
                float* __restrict__ out) {
    __shared__ float As[64 * 64];
    __shared__ float Ws[64 * 64];
    __shared__ float W2s[64 * 2];
    __shared__ float b2s[2];
    int nbase = blockIdx.x * 64;

    for (int i = threadIdx.x; i < 64 * 64; i += 256) Ws[i] = W1[i];
    if (threadIdx.x < 128) W2s[threadIdx.x] = W2[threadIdx.x];
    if (threadIdx.x < 2) b2s[threadIdx.x] = b2[threadIdx.x];
    for (int i = threadIdx.x; i < 64 * 64; i += 256) {
        int nd = i >> 6, k = i & 63;
        int gn = nbase + nd;
        As[i] = (gn < NN) ? g_h[gn * H + k] : 0.f;
    }
    __syncthreads();

    int tn = threadIdx.x & 15, te = threadIdx.x >> 4;
    float acc[4][4] = {};
    for (int k = 0; k < 64; k += 4) {
        float4 av4[4];
#pragma unroll
        for (int i = 0; i < 4; i++)
            av4[i] = *(const float4*)(As + (te * 4 + i) * 64 + k);
        const float* av = (const float*)av4;
#pragma unroll
        for (int kk = 0; kk < 4; kk++) {
            float4 w = *(const float4*)(Ws + (k + kk) * H + tn * 4);
#pragma unroll
            for (int i = 0; i < 4; i++) {
                float a = av[i * 4 + kk];
                acc[i][0] += a * w.x;
                acc[i][1] += a * w.y;
                acc[i][2] += a * w.z;
                acc[i][3] += a * w.w;
            }
        }
    }
    __syncthreads();

    float4 bv = *(const float4*)(b1 + tn * 4);
    const float* bvp = (const float*)&bv;
#pragma unroll
    for (int i = 0; i < 4; i++)
#pragma unroll
        for (int j = 0; j < 4; j++)
            As[(tn * 4 + j) * 64 + te * 4 + i] = fmaxf(acc[i][j] + bvp[j], 0.f);
    __syncthreads();

    if (threadIdx.x < 128) {
        int nd = threadIdx.x & 63, j = threadIdx.x >> 6;
        int gn = nbase + nd;
        if (gn < NN) {
            float s = b2s[j];
#pragma unroll 8
            for (int k = 0; k < 64; k++) s += As[k * 64 + nd] * W2s[k * 2 + j];
            out[gn * 2 + j] = s;
        }
    }
}

// ---------------------------------------------------------------------------
// Edge head (bf16x3 MMA, fused): 136 -> 128 -> 64 -> 6, tile 64 edges.
// ---------------------------------------------------------------------------
#define STRW1 136    // 8 mod 32
#define C2STR 65     // 1 mod 32 (scalar reads conflict-free)
#define EH_SMEM ((2*64*STRA + 2*72*STRW1) * 4)    // 117248 B

__global__ void __launch_bounds__(256)
edgehead_kernel(const int* __restrict__ ei, const float* __restrict__ ea,
                const float* __restrict__ b1, const float* __restrict__ b2,
                const float* __restrict__ W3, const float* __restrict__ b3,
                float* __restrict__ out) {
    extern __shared__ uint32_t sm32[];
    uint32_t* Ah = sm32;                 // [64][76]  F pk, later C1 pk
    uint32_t* Al = Ah + 64 * STRA;
    uint32_t* Wh = Al + 64 * STRA;       // [72][136] W1 pk, later W2/C2/W3
    uint32_t* Wl = Wh + 72 * STRW1;
    const int* src = ei;
    const int* dst = ei + EE;
    const int ebase = blockIdx.x * 64;
    const int tid = threadIdx.x;

    for (int i = tid; i < 72 * STRW1; i += 256) { Wh[i] = g_We1_h[i]; Wl[i] = g_We1_l[i]; }
    for (int i = tid; i < 64 * 72; i += 256) {
        int e = i / 72, kp = i - e * 72;
        int ge = ebase + e;
        float2 v;
        if (kp < 32)      v = *(const float2*)(g_h + src[ge] * H + 2 * kp);
        else if (kp < 64) v = *(const float2*)(g_h + dst[ge] * H + 2 * (kp - 32));
        else if (kp < 68) v = *(const float2*)(ea + ge * EAD + 2 * (kp - 64));
        else              v = make_float2(0.f, 0.f);
        splitpack(v.x, v.y, Ah[e * STRA + kp], Al[e * STRA + kp]);
    }
    __syncthreads();

    const int lane = tid & 31, warp = tid >> 5;
    const int g = lane >> 2, tig = lane & 3;
    const int warpM = warp & 3, warpN = warp >> 2;
    const int row0 = warpM * 16 + g;

    // GEMM1: [64,136] @ [136,128] ; warp tile 16 x 64 (8 n-tiles)
    float acc1[8][4] = {};
#pragma unroll
    for (int s = 0; s < 9; s++) {
        const int k0p = s * 8;
        uint32_t ah[4], al[4];
        ah[0] = Ah[ row0      * STRA + k0p + tig    ];
        ah[1] = Ah[(row0 + 8) * STRA + k0p + tig    ];
        ah[2] = Ah[ row0      * STRA + k0p + tig + 4];
        ah[3] = Ah[(row0 + 8) * STRA + k0p + tig + 4];
        al[0] = Al[ row0      * STRA + k0p + tig    ];
        al[1] = Al[(row0 + 8) * STRA + k0p + tig    ];
        al[2] = Al[ row0      * STRA + k0p + tig + 4];
        al[3] = Al[(row0 + 8) * STRA + k0p + tig + 4];
#pragma unroll
        for (int nt = 0; nt < 8; nt++) {
            int n = warpN * 64 + nt * 8 + g;
            uint32_t bh0 = Wh[(k0p + tig)     * STRW1 + n];
            uint32_t bh1 = Wh[(k0p + tig + 4) * STRW1 + n];
            uint32_t bl0 = Wl[(k0p + tig)     * STRW1 + n];
            uint32_t bl1 = Wl[(k0p + tig + 4) * STRW1 + n];
            mma_bf16(acc1[nt], ah, bh0, bh1);
            mma_bf16(acc1[nt], al, bh0, bh1);
            mma_bf16(acc1[nt], ah, bl0, bl1);
        }
    }
    __syncthreads();   // done reading F/W1

    // epilogue1: C1 = relu(acc1 + b1), split-packed into Ah/Al (pairs over n)
#pragma unroll
    for (int nt = 0; nt < 8; nt++) {
        int n = warpN * 64 + nt * 8 + 2 * tig;
        int kp2 = n >> 1;                      // pair index for GEMM2
        float bb0 = __ldg(b1 + n), bb1 = __ldg(b1 + n + 1);
        splitpack(fmaxf(acc1[nt][0] + bb0, 0.f), fmaxf(acc1[nt][1] + bb1, 0.f),
                  Ah[row0 * STRA + kp2], Al[row0 * STRA + kp2]);
        splitpack(fmaxf(acc1[nt][2] + bb0, 0.f), fmaxf(acc1[nt][3] + bb1, 0.f),
                  Ah[(row0 + 8) * STRA + kp2], Al[(row0 + 8) * STRA + kp2]);
    }
    // load W2 pk into reused W region
    uint32_t* W2h = Wh;                 // [64][72]
    uint32_t* W2l = Wh + 64 * STRB;
    for (int i = tid; i < 64 * STRB; i += 256) { W2h[i] = g_We2_h[i]; W2l[i] = g_We2_l[i]; }
    __syncthreads();

    // GEMM2: [64,128] @ [128,64] ; warp tile 16 x 32 (4 n-tiles)
    float acc2[4][4] = {};
#pragma unroll
    for (int s = 0; s < 8; s++) {
        const int k0p = s * 8;
        uint32_t ah[4], al[4];
        ah[0] = Ah[ row0      * STRA + k0p + tig    ];
        ah[1] = Ah[(row0 + 8) * STRA + k0p + tig    ];
        ah[2] = Ah[ row0      * STRA + k0p + tig + 4];
        ah[3] = Ah[(row0 + 8) * STRA + k0p + tig + 4];
        al[0] = Al[ row0      * STRA + k0p + tig    ];
        al[1] = Al[(row0 + 8) * STRA + k0p + tig    ];
        al[2] = Al[ row0      * STRA + k0p + tig + 4];
        al[3] = Al[(row0 + 8) * STRA + k0p + tig + 4];
#pragma unroll
        for (int nt = 0; nt < 4; nt++) {
            int n = warpN * 32 + nt * 8 + g;
            uint32_t bh0 = W2h[(k0p + tig)     * STRB + n];
            uint32_t bh1 = W2h[(k0p + tig + 4) * STRB + n];
            uint32_t bl0 = W2l[(k0p + tig)     * STRB + n];
            uint32_t bl1 = W2l[(k0p + tig + 4) * STRB + n];
            mma_bf16(acc2[nt], ah, bh0, bh1);
            mma_bf16(acc2[nt], al, bh0, bh1);
            mma_bf16(acc2[nt], ah, bl0, bl1);
        }
    }
    __syncthreads();   // done reading C1/W2

    // epilogue2: C2 = relu(acc2 + b2) -> fp32 [64][65] ; load W3/b3
    float* bufC = (float*)(Wh + 2 * 64 * STRB);   // 64*65 floats
    float* W3s  = bufC + 64 * C2STR;              // 384 floats
    float* b3s  = W3s + 384;                      // 6 floats
#pragma unroll
    for (int nt = 0; nt < 4; nt++) {
        int n = warpN * 32 + nt * 8 + 2 * tig;
        float bb0 = __ldg(b2 + n), bb1 = __ldg(b2 + n + 1);
        bufC[ row0      * C2STR + n    ] = fmaxf(acc2[nt][0] + bb0, 0.f);
        bufC[ row0      * C2STR + n + 1] = fmaxf(acc2[nt][1] + bb1, 0.f);
        bufC[(row0 + 8) * C2STR + n    ] = fmaxf(acc2[nt][2] + bb0, 0.f);
        bufC[(row0 + 8) * C2STR + n + 1] = fmaxf(acc2[nt][3] + bb1, 0.f);
    }
    for (int i = tid; i < 384; i += 256) W3s[i] = W3[i];
    if (tid < 6) b3s[tid] = b3[tid];
    __syncthreads();

    // GEMM3: [64,64] @ [64,6] -> out
    for (int t = tid; t < 384; t += 256) {
        int e = t & 63, j = t >> 6;
        float s = b3s[j];
#pragma unroll 8
        for (int k = 0; k < 64; k++) s += bufC[e * C2STR + k] * W3s[k * 6 + j];
        out[(ebase + e) * 6 + j] = s;
    }
}

// ---------------------------------------------------------------------------

extern "C" void kernel_launch(void* const* d_in, const int* in_sizes, int n_in,
                              void* d_out, int out_size) {
    const float* x     = (const float*)d_in[0];
    const int*   ei    = (const int*)d_in[1];
    const float* ea    = (const float*)d_in[2];
    const float* W_enc = (const float*)d_in[3];
    const float* b_enc = (const float*)d_in[4];
    const float* W_msg = (const float*)d_in[5];
    const float* b_msg = (const float*)d_in[6];
    const float* W_upd = (const float*)d_in[7];
    const float* b_upd = (const float*)d_in[8];
    const float* W_nd1 = (const float*)d_in[9];
    const float* b_nd1 = (const float*)d_in[10];
    const float* W_nd2 = (const float*)d_in[11];
    const float* b_nd2 = (const float*)d_in[12];
    const float* W_ed1 = (const float*)d_in[13];
    const float* b_ed1 = (const float*)d_in[14];
    const float* W_ed2 = (const float*)d_in[15];
    const float* b_ed2 = (const float*)d_in[16];
    const float* W_ed3 = (const float*)d_in[17];
    const float* b_ed3 = (const float*)d_in[18];
    float* out = (float*)d_out;

    cudaFuncSetAttribute(msg_kernel, cudaFuncAttributeMaxDynamicSharedMemorySize, MSG_SMEM);
    cudaFuncSetAttribute(upd_kernel, cudaFuncAttributeMaxDynamicSharedMemorySize, UPD_SMEM);
    cudaFuncSetAttribute(edgehead_kernel, cudaFuncAttributeMaxDynamicSharedMemorySize, EH_SMEM);

    split_all_kernel<<<(SPLIT_TOTAL + 255) / 256, 256>>>(W_msg, W_upd, W_ed1, W_ed2);
    enc_kernel<<<(NN + 255) / 256, 256>>>(x, W_enc, b_enc);
    for (int l = 0; l < 3; l++) {
        zero_agg_kernel<<<(NN * H + 255) / 256, 256>>>();
        msg_kernel<<<EE / 64, 256, MSG_SMEM>>>(ei, ea, b_msg);
        upd_kernel<<<(NN + 63) / 64, 256, UPD_SMEM>>>(b_upd);
    }
    nodehead_kernel<<<(NN + 63) / 64, 256>>>(W_nd1, b_nd1, W_nd2, b_nd2, out);
    edgehead_kernel<<<EE / 64, 256, EH_SMEM>>>(ei, ea, b_ed1, b_ed2, W_ed3, b_ed3,
                                               out + 2 * NN);
}

// round 6
// speedup vs baseline: 2.6575x; 2.0824x over previous
#include <cuda_runtime.h>
#include <cstdint>

#define NN 50000
#define EE 800000
#define IND 16
#define H 64
#define EAD 8
#define KM (2*H + EAD)   // 136

#define GRID_P 148       // persistent grid = #SMs

// Scratch state (no cudaMalloc allowed)
__device__ float g_h[NN * H];       // fp32 h (nodehead input)
__device__ float g_agg[NN * H];     // per-round aggregation buffer
__device__ uint32_t g_hh[NN * 32];  // h packed bf16x2 hi (pairs over k)
__device__ uint32_t g_hl[NN * 32];  // h packed bf16x2 lo
__device__ uint32_t g_eah[EE * 4];  // edge_attr packed hi
__device__ uint32_t g_eal[EE * 4];  // edge_attr packed lo

// Pre-split packed bf16x2 weights (hi/lo), [k_pair][n] with smem strides
__device__ uint32_t g_Wmsg_h[72 * 72],  g_Wmsg_l[72 * 72];
__device__ uint32_t g_Wupd_h[64 * 72],  g_Wupd_l[64 * 72];
__device__ uint32_t g_We1_h[72 * 136],  g_We1_l[72 * 136];
__device__ uint32_t g_We2_h[64 * 72],   g_We2_l[64 * 72];

// ---------------------------------------------------------------------------
// helpers
// ---------------------------------------------------------------------------
__device__ __forceinline__ void splitpack(float a0, float a1, uint32_t& hi, uint32_t& lo) {
    uint32_t h, l;
    asm("cvt.rn.bf16x2.f32 %0, %1, %2;" : "=r"(h) : "f"(a1), "f"(a0));
    float r0 = a0 - __uint_as_float(h << 16);
    float r1 = a1 - __uint_as_float(h & 0xFFFF0000u);
    asm("cvt.rn.bf16x2.f32 %0, %1, %2;" : "=r"(l) : "f"(r1), "f"(r0));
    hi = h; lo = l;
}

__device__ __forceinline__ void mma_bf16(float* c, const uint32_t* a, uint32_t b0, uint32_t b1) {
    asm volatile(
        "mma.sync.aligned.m16n8k16.row.col.f32.bf16.bf16.f32 "
        "{%0,%1,%2,%3}, {%4,%5,%6,%7}, {%8,%9}, {%0,%1,%2,%3};"
        : "+f"(c[0]), "+f"(c[1]), "+f"(c[2]), "+f"(c[3])
        : "r"(a[0]), "r"(a[1]), "r"(a[2]), "r"(a[3]), "r"(b0), "r"(b1));
}

#define CP_ASYNC16(saddr, gptr) \
    asm volatile("cp.async.cg.shared.global [%0], [%1], 16;" :: "r"(saddr), "l"(gptr) : "memory")
#define CP_COMMIT() asm volatile("cp.async.commit_group;" ::: "memory")
#define CP_WAIT1()  asm volatile("cp.async.wait_group 1;" ::: "memory")

// ---------------------------------------------------------------------------
// Setup kernels
// ---------------------------------------------------------------------------
__device__ __forceinline__ void split_one(const float* W, int K2, int N, int STR,
                                          uint32_t* oh, uint32_t* ol, int i) {
    int kp = i / STR, n = i - kp * STR;
    float a0 = 0.f, a1 = 0.f;
    if (n < N && kp < K2) { a0 = W[(2 * kp) * N + n]; a1 = W[(2 * kp + 1) * N + n]; }
    uint32_t h, l; splitpack(a0, a1, h, l);
    oh[i] = h; ol[i] = l;
}

#define SZ_MSG (72*72)
#define SZ_UPD (64*72)
#define SZ_E1  (72*136)
#define SZ_E2  (64*72)
#define SPLIT_TOTAL (SZ_MSG + SZ_UPD + SZ_E1 + SZ_E2)

__global__ void split_all_kernel(const float* __restrict__ Wm, const float* __restrict__ Wu,
                                 const float* __restrict__ W1, const float* __restrict__ W2) {
    int i = blockIdx.x * 256 + threadIdx.x;
    if (i < SZ_MSG) { split_one(Wm, 68, 64, 72, g_Wmsg_h, g_Wmsg_l, i); return; }
    i -= SZ_MSG;
    if (i < SZ_UPD) { split_one(Wu, 64, 64, 72, g_Wupd_h, g_Wupd_l, i); return; }
    i -= SZ_UPD;
    if (i < SZ_E1)  { split_one(W1, 68, 128, 136, g_We1_h, g_We1_l, i); return; }
    i -= SZ_E1;
    if (i < SZ_E2)  { split_one(W2, 64, 64, 72, g_We2_h, g_We2_l, i); return; }
}

__global__ void split_ea_kernel(const float* __restrict__ ea) {
    int i = blockIdx.x * 256 + threadIdx.x;
    if (i >= EE * 4) return;
    int ge = i >> 2, j = i & 3;
    float2 v = *(const float2*)(ea + ge * EAD + 2 * j);
    splitpack(v.x, v.y, g_eah[i], g_eal[i]);
}

// ---------------------------------------------------------------------------
// Encoder: h = x @ W_enc + b_enc ; writes fp32 h + packed hi/lo
// ---------------------------------------------------------------------------
__global__ void enc_kernel(const float* __restrict__ x,
                           const float* __restrict__ W,
                           const float* __restrict__ b) {
    __shared__ float Ws[IND * H];
    __shared__ float bs[H];
    for (int i = threadIdx.x; i < IND * H; i += blockDim.x) Ws[i] = W[i];
    if (threadIdx.x < H) bs[threadIdx.x] = b[threadIdx.x];
    __syncthreads();
    int node = blockIdx.x * blockDim.x + threadIdx.x;
    if (node >= NN) return;
    float xv[IND];
#pragma unroll
    for (int k = 0; k < IND; k++) xv[k] = x[node * IND + k];
#pragma unroll 4
    for (int n = 0; n < H; n += 2) {
        float a0 = bs[n], a1 = bs[n + 1];
#pragma unroll
        for (int k = 0; k < IND; k++) {
            a0 += xv[k] * Ws[k * H + n];
            a1 += xv[k] * Ws[k * H + n + 1];
        }
        g_h[node * H + n] = a0;
        g_h[node * H + n + 1] = a1;
        splitpack(a0, a1, g_hh[node * 32 + n / 2], g_hl[node * 32 + n / 2]);
    }
}

__global__ void zero_agg_kernel() {
    int i = blockIdx.x * blockDim.x + threadIdx.x;
    if (i < NN * H) g_agg[i] = 0.f;
}

// ---------------------------------------------------------------------------
// Message + scatter-add: persistent, double-buffered, tile = 128 edges
// ---------------------------------------------------------------------------
#define STRA 76     // A pair-stride (12 mod 32)
#define STRB 72     // B pair-stride ( 8 mod 32)
#define MT 128
#define NT_MSG (EE / MT)         // 6250
#define AB (MT * STRA)           // uints per half-buffer (9728)
#define MSG_SMEM ((4*AB + 2*72*STRB) * 4)   // 197120 B

__device__ __forceinline__ void msg_stage(uint32_t* buf,
        const int* __restrict__ src, const int* __restrict__ dst,
        int tbase, int tid) {
    int e = tid >> 1, sub = tid & 1;            // 2 threads per edge
    int ge = tbase + e;
    int s = src[ge], d = dst[ge];
    uint32_t* row = buf + sub * AB + e * STRA;  // sub0 -> hi, sub1 -> lo
    const uint32_t* gh = sub ? g_hl : g_hh;
    const uint32_t* ge4 = (sub ? g_eal : g_eah) + ge * 4;
    uint32_t rb = (uint32_t)__cvta_generic_to_shared(row);
    const uint32_t* ps = gh + s * 32;
    const uint32_t* pd = gh + d * 32;
#pragma unroll
    for (int j = 0; j < 8; j++) CP_ASYNC16(rb + j * 16, ps + j * 4);
#pragma unroll
    for (int j = 0; j < 8; j++) CP_ASYNC16(rb + 128 + j * 16, pd + j * 4);
    CP_ASYNC16(rb + 256, ge4);
}

__global__ void __launch_bounds__(256, 1)
msg_kernel(const int* __restrict__ ei, const float* __restrict__ b) {
    extern __shared__ uint32_t sm32[];
    uint32_t* Bh = sm32 + 4 * AB;
    uint32_t* Bl = Bh + 72 * STRB;
    const int* src = ei;
    const int* dst = ei + EE;
    const int tid = threadIdx.x;

    for (int i = tid; i < 72 * STRB; i += 256) { Bh[i] = g_Wmsg_h[i]; Bl[i] = g_Wmsg_l[i]; }
    // zero K-pad (pairs 68..75) in all 4 half-buffers
    for (int i = tid; i < MT * 8; i += 256) {
        int e = i >> 3, j = i & 7;
        sm32[0 * AB + e * STRA + 68 + j] = 0;
        sm32[1 * AB + e * STRA + 68 + j] = 0;
        sm32[2 * AB + e * STRA + 68 + j] = 0;
        sm32[3 * AB + e * STRA + 68 + j] = 0;
    }

    const int lane = tid & 31, warp = tid >> 5;
    const int g = lane >> 2, tig = lane & 3;
    const int row0 = warp * 16 + g;

    float2 bias[8];
#pragma unroll
    for (int nt = 0; nt < 8; nt++) {
        int n = nt * 8 + 2 * tig;
        bias[nt] = make_float2(__ldg(b + n), __ldg(b + n + 1));
    }
    __syncthreads();

    int t = blockIdx.x, cur = 0;
    if (t < NT_MSG) msg_stage(sm32, src, dst, t * MT, tid);
    CP_COMMIT();

    for (; t < NT_MSG; t += GRID_P) {
        int tn = t + GRID_P;
        if (tn < NT_MSG) msg_stage(sm32 + (cur ^ 1) * 2 * AB, src, dst, tn * MT, tid);
        CP_COMMIT();
        CP_WAIT1();
        __syncthreads();

        const uint32_t* Ah = sm32 + cur * 2 * AB;
        const uint32_t* Al = Ah + AB;
        float acc[8][4] = {};
#pragma unroll
        for (int s = 0; s < 9; s++) {
            const int k0p = s * 8;
            uint32_t ah[4], al[4];
            ah[0] = Ah[ row0      * STRA + k0p + tig    ];
            ah[1] = Ah[(row0 + 8) * STRA + k0p + tig    ];
            ah[2] = Ah[ row0      * STRA + k0p + tig + 4];
            ah[3] = Ah[(row0 + 8) * STRA + k0p + tig + 4];
            al[0] = Al[ row0      * STRA + k0p + tig    ];
            al[1] = Al[(row0 + 8) * STRA + k0p + tig    ];
            al[2] = Al[ row0      * STRA + k0p + tig + 4];
            al[3] = Al[(row0 + 8) * STRA + k0p + tig + 4];
#pragma unroll
            for (int nt = 0; nt < 8; nt++) {
                int n = nt * 8 + g;
                uint32_t bh0 = Bh[(k0p + tig)     * STRB + n];
                uint32_t bh1 = Bh[(k0p + tig + 4) * STRB + n];
                uint32_t bl0 = Bl[(k0p + tig)     * STRB + n];
                uint32_t bl1 = Bl[(k0p + tig + 4) * STRB + n];
                mma_bf16(acc[nt], ah, bh0, bh1);
                mma_bf16(acc[nt], al, bh0, bh1);
                mma_bf16(acc[nt], ah, bl0, bl1);
            }
        }

        const int tbase = t * MT;
        const int d0 = dst[tbase + row0];
        const int d1 = dst[tbase + row0 + 8];
#pragma unroll
        for (int nt = 0; nt < 8; nt++) {
            int n = nt * 8 + 2 * tig;
            float2 v01 = make_float2(fmaxf(acc[nt][0] + bias[nt].x, 0.f),
                                     fmaxf(acc[nt][1] + bias[nt].y, 0.f));
            float2 v23 = make_float2(fmaxf(acc[nt][2] + bias[nt].x, 0.f),
                                     fmaxf(acc[nt][3] + bias[nt].y, 0.f));
            atomicAdd((float2*)(g_agg + d0 * H + n), v01);
            atomicAdd((float2*)(g_agg + d1 * H + n), v23);
        }
        __syncthreads();
        cur ^= 1;
    }
}

// ---------------------------------------------------------------------------
// Update: h = relu([h | agg] @ W_upd + b) ; packed-h staging, writes both forms
// ---------------------------------------------------------------------------
#define UPD_SMEM ((2*64*STRA + 2*64*STRB) * 4)    // 75776 B

__global__ void __launch_bounds__(256, 2)
upd_kernel(const float* __restrict__ b) {
    extern __shared__ uint32_t sm32[];
    uint32_t* Ah = sm32;
    uint32_t* Al = Ah + 64 * STRA;
    uint32_t* Bh = Al + 64 * STRA;
    uint32_t* Bl = Bh + 64 * STRB;
    const int nbase = blockIdx.x * 64;
    const int tid = threadIdx.x;

    for (int i = tid; i < 64 * STRB; i += 256) { Bh[i] = g_Wupd_h[i]; Bl[i] = g_Wupd_l[i]; }
    for (int i = tid; i < 64 * 64; i += 256) {
        int nd = i >> 6, kp = i & 63;
        int gn = nbase + nd;
        uint32_t h = 0, l = 0;
        if (gn < NN) {
            if (kp < 32) { h = g_hh[gn * 32 + kp]; l = g_hl[gn * 32 + kp]; }
            else {
                float2 v = *(const float2*)(g_agg + gn * H + 2 * (kp - 32));
                splitpack(v.x, v.y, h, l);
            }
        }
        Ah[nd * STRA + kp] = h;
        Al[nd * STRA + kp] = l;
    }
    __syncthreads();

    const int lane = tid & 31, warp = tid >> 5;
    const int g = lane >> 2, tig = lane & 3;
    const int warpM = warp & 3, warpN = warp >> 2;
    const int row0 = warpM * 16 + g;

    float acc[4][4] = {};
#pragma unroll
    for (int s = 0; s < 8; s++) {
        const int k0p = s * 8;
        uint32_t ah[4], al[4];
        ah[0] = Ah[ row0      * STRA + k0p + tig    ];
        ah[1] = Ah[(row0 + 8) * STRA + k0p + tig    ];
        ah[2] = Ah[ row0      * STRA + k0p + tig + 4];
        ah[3] = Ah[(row0 + 8) * STRA + k0p + tig + 4];
        al[0] = Al[ row0      * STRA + k0p + tig    ];
        al[1] = Al[(row0 + 8) * STRA + k0p + tig    ];
        al[2] = Al[ row0      * STRA + k0p + tig + 4];
        al[3] = Al[(row0 + 8) * STRA + k0p + tig + 4];
#pragma unroll
        for (int nt = 0; nt < 4; nt++) {
            int n = warpN * 32 + nt * 8 + g;
            uint32_t bh0 = Bh[(k0p + tig)     * STRB + n];
            uint32_t bh1 = Bh[(k0p + tig + 4) * STRB + n];
            uint32_t bl0 = Bl[(k0p + tig)     * STRB + n];
            uint32_t bl1 = Bl[(k0p + tig + 4) * STRB + n];
            mma_bf16(acc[nt], ah, bh0, bh1);
            mma_bf16(acc[nt], al, bh0, bh1);
            mma_bf16(acc[nt], ah, bl0, bl1);
        }
    }

    const int gn0 = nbase + row0, gn1 = nbase + row0 + 8;
#pragma unroll
    for (int nt = 0; nt < 4; nt++) {
        int n = warpN * 32 + nt * 8 + 2 * tig;
        int kp = n >> 1;
        float bb0 = __ldg(b + n), bb1 = __ldg(b + n + 1);
        if (gn0 < NN) {
            float v0 = fmaxf(acc[nt][0] + bb0, 0.f);
            float v1 = fmaxf(acc[nt][1] + bb1, 0.f);
            *(float2*)(g_h + gn0 * H + n) = make_float2(v0, v1);
            splitpack(v0, v1, g_hh[gn0 * 32 + kp], g_hl[gn0 * 32 + kp]);
        }
        if (gn1 < NN) {
            float v0 = fmaxf(acc[nt][2] + bb0, 0.f);
            float v1 = fmaxf(acc[nt][3] + bb1, 0.f);
            *(float2*)(g_h + gn1 * H + n) = make_float2(v0, v1);
            splitpack(v0, v1, g_hh[gn1 * 32 + kp], g_hl[gn1 * 32 + kp]);
        }
    }
}

// ---------------------------------------------------------------------------
// Node head (FFMA): out = relu(h @ W1 + b1) @ W2 + b2
// ---------------------------------------------------------------------------
__global__ void __launch_bounds__(256)
nodehead_kernel(const float* __restrict__ W1, const float* __restrict__ b1,
                const float* __restrict__ W2, const float* __restrict__ b2,
                float* __restrict__ out) {
    __shared__ float As[64 * 64];
    __shared__ float Ws[64 * 64];
    __shared__ float W2s[64 * 2];
    __shared__ float b2s[2];
    int nbase = blockIdx.x * 64;

    for (int i = threadIdx.x; i < 64 * 64; i += 256) Ws[i] = W1[i];
    if (threadIdx.x < 128) W2s[threadIdx.x] = W2[threadIdx.x];
    if (threadIdx.x < 2) b2s[threadIdx.x] = b2[threadIdx.x];
    for (int i = threadIdx.x; i < 64 * 64; i += 256) {
        int nd = i >> 6, k = i & 63;
        int gn = nbase + nd;
        As[i] = (gn < NN) ? g_h[gn * H + k] : 0.f;
    }
    __syncthreads();

    int tn = threadIdx.x & 15, te = threadIdx.x >> 4;
    float acc[4][4] = {};
    for (int k = 0; k < 64; k += 4) {
        float4 av4[4];
#pragma unroll
        for (int i = 0; i < 4; i++)
            av4[i] = *(const float4*)(As + (te * 4 + i) * 64 + k);
        const float* av = (const float*)av4;
#pragma unroll
        for (int kk = 0; kk < 4; kk++) {
            float4 w = *(const float4*)(Ws + (k + kk) * H + tn * 4);
#pragma unroll
            for (int i = 0; i < 4; i++) {
                float a = av[i * 4 + kk];
                acc[i][0] += a * w.x;
                acc[i][1] += a * w.y;
                acc[i][2] += a * w.z;
                acc[i][3] += a * w.w;
            }
        }
    }
    __syncthreads();

    float4 bv = *(const float4*)(b1 + tn * 4);
    const float* bvp = (const float*)&bv;
#pragma unroll
    for (int i = 0; i < 4; i++)
#pragma unroll
        for (int j = 0; j < 4; j++)
            As[(tn * 4 + j) * 64 + te * 4 + i] = fmaxf(acc[i][j] + bvp[j], 0.f);
    __syncthreads();

    if (threadIdx.x < 128) {
        int nd = threadIdx.x & 63, j = threadIdx.x >> 6;
        int gn = nbase + nd;
        if (gn < NN) {
            float s = b2s[j];
#pragma unroll 8
            for (int k = 0; k < 64; k++) s += As[k * 64 + nd] * W2s[k * 2 + j];
            out[gn * 2 + j] = s;
        }
    }
}

// ---------------------------------------------------------------------------
// Edge head: persistent, all weights resident, double-buffered F staging.
// 136 -> 128 -> 64 -> 6, tile 64 edges. C1/C2 alias the current F buffer.
// ---------------------------------------------------------------------------
#define STRW1 136
#define ET 64
#define NT_EH (EE / ET)      // 12500
#define EAB (ET * STRA)      // 4864 uints per half-buffer
#define EH_SMEM ((4*EAB + 2*72*STRW1 + 2*64*STRB) * 4 + 390 * 4)   // 194584 B

__device__ __forceinline__ void eh_stage(uint32_t* buf,
        const int* __restrict__ src, const int* __restrict__ dst,
        int tbase, int tid) {
    int e = tid >> 2, sub = tid & 3;            // 4 threads per edge
    int ge = tbase + e;
    int lo = sub >> 1;                          // 0 = hi, 1 = lo
    uint32_t* row = buf + lo * EAB + e * STRA;
    const uint32_t* gh = lo ? g_hl : g_hh;
    uint32_t rb = (uint32_t)__cvta_generic_to_shared(row);
    if ((sub & 1) == 0) {                       // src half + ea
        const uint32_t* p = gh + src[ge] * 32;
#pragma unroll
        for (int j = 0; j < 8; j++) CP_ASYNC16(rb + j * 16, p + j * 4);
        CP_ASYNC16(rb + 256, (lo ? g_eal : g_eah) + ge * 4);
    } else {                                    // dst half
        const uint32_t* p = gh + dst[ge] * 32;
#pragma unroll
        for (int j = 0; j < 8; j++) CP_ASYNC16(rb + 128 + j * 16, p + j * 4);
    }
}

__global__ void __launch_bounds__(256, 1)
edgehead_kernel(const int* __restrict__ ei,
                const float* __restrict__ b1, const float* __restrict__ b2,
                const float* __restrict__ W3, const float* __restrict__ b3,
                float* __restrict__ out) {
    extern __shared__ uint32_t sm32[];
    uint32_t* W1h = sm32 + 4 * EAB;
    uint32_t* W1l = W1h + 72 * STRW1;
    uint32_t* W2h = W1l + 72 * STRW1;
    uint32_t* W2l = W2h + 64 * STRB;
    float*    W3s = (float*)(W2l + 64 * STRB);   // 384 floats
    float*    b3s = W3s + 384;                   // 6 floats
    const int* src = ei;
    const int* dst = ei + EE;
    const int tid = threadIdx.x;

    for (int i = tid; i < 72 * STRW1; i += 256) { W1h[i] = g_We1_h[i]; W1l[i] = g_We1_l[i]; }
    for (int i = tid; i < 64 * STRB; i += 256)  { W2h[i] = g_We2_h[i]; W2l[i] = g_We2_l[i]; }
    for (int i = tid; i < 384; i += 256) W3s[i] = W3[i];
    if (tid < 6) b3s[tid] = b3[tid];
    // zero K-pad (pairs 68..75) in all 4 half-buffers
    for (int i = tid; i < ET * 8; i += 256) {
        int e = i >> 3, j = i & 7;
        sm32[0 * EAB + e * STRA + 68 + j] = 0;
        sm32[1 * EAB + e * STRA + 68 + j] = 0;
        sm32[2 * EAB + e * STRA + 68 + j] = 0;
        sm32[3 * EAB + e * STRA + 68 + j] = 0;
    }

    const int lane = tid & 31, warp = tid >> 5;
    const int g = lane >> 2, tig = lane & 3;
    const int warpM = warp & 3, warpN = warp >> 2;
    const int row0 = warpM * 16 + g;
    __syncthreads();

    int t = blockIdx.x, cur = 0;
    if (t < NT_EH) eh_stage(sm32, src, dst, t * ET, tid);
    CP_COMMIT();

    for (; t < NT_EH; t += GRID_P) {
        int tn = t + GRID_P;
        if (tn < NT_EH) eh_stage(sm32 + (cur ^ 1) * 2 * EAB, src, dst, tn * ET, tid);
        CP_COMMIT();
        CP_WAIT1();
        __syncthreads();

        uint32_t* Ah = sm32 + cur * 2 * EAB;
        uint32_t* Al = Ah + EAB;
        const int ebase = t * ET;

        // GEMM1: [64,136] @ [136,128] ; warp 16x64 (8 n-tiles)
        float acc1[8][4] = {};
#pragma unroll
        for (int s = 0; s < 9; s++) {
            const int k0p = s * 8;
            uint32_t ah[4], al[4];
            ah[0] = Ah[ row0      * STRA + k0p + tig    ];
            ah[1] = Ah[(row0 + 8) * STRA + k0p + tig    ];
            ah[2] = Ah[ row0      * STRA + k0p + tig + 4];
            ah[3] = Ah[(row0 + 8) * STRA + k0p + tig + 4];
            al[0] = Al[ row0      * STRA + k0p + tig    ];
            al[1] = Al[(row0 + 8) * STRA + k0p + tig    ];
            al[2] = Al[ row0      * STRA + k0p + tig + 4];
            al[3] = Al[(row0 + 8) * STRA + k0p + tig + 4];
#pragma unroll
            for (int nt = 0; nt < 8; nt++) {
                int n = warpN * 64 + nt * 8 + g;
                uint32_t bh0 = W1h[(k0p + tig)     * STRW1 + n];
                uint32_t bh1 = W1h[(k0p + tig + 4) * STRW1 + n];
                uint32_t bl0 = W1l[(k0p + tig)     * STRW1 + n];
                uint32_t bl1 = W1l[(k0p + tig + 4) * STRW1 + n];
                mma_bf16(acc1[nt], ah, bh0, bh1);
                mma_bf16(acc1[nt], al, bh0, bh1);
                mma_bf16(acc1[nt], ah, bl0, bl1);
            }
        }
        __syncthreads();   // F reads done -> safe to overwrite with C1

        // epilogue1: C1 = splitpack(relu(acc1 + b1)) into Ah/Al (kp = n/2)
#pragma unroll
        for (int nt = 0; nt < 8; nt++) {
            int n = warpN * 64 + nt * 8 + 2 * tig;
            int kp2 = n >> 1;
            float bb0 = __ldg(b1 + n), bb1 = __ldg(b1 + n + 1);
            splitpack(fmaxf(acc1[nt][0] + bb0, 0.f), fmaxf(acc1[nt][1] + bb1, 0.f),
                      Ah[row0 * STRA + kp2], Al[row0 * STRA + kp2]);
            splitpack(fmaxf(acc1[nt][2] + bb0, 0.f), fmaxf(acc1[nt][3] + bb1, 0.f),
                      Ah[(row0 + 8) * STRA + kp2], Al[(row0 + 8) * STRA + kp2]);
        }
        __syncthreads();

        // GEMM2: [64,128] @ [128,64] ; warp 16x32 (4 n-tiles)
        float acc2[4][4] = {};
#pragma unroll
        for (int s = 0; s < 8; s++) {
            const int k0p = s * 8;
            uint32_t ah[4], al[4];
            ah[0] = Ah[ row0      * STRA + k0p + tig    ];
            ah[1] = Ah[(row0 + 8) * STRA + k0p + tig    ];
            ah[2] = Ah[ row0      * STRA + k0p + tig + 4];
            ah[3] = Ah[(row0 + 8) * STRA + k0p + tig + 4];
            al[0] = Al[ row0      * STRA + k0p + tig    ];
            al[1] = Al[(row0 + 8) * STRA + k0p + tig    ];
            al[2] = Al[ row0      * STRA + k0p + tig + 4];
            al[3] = Al[(row0 + 8) * STRA + k0p + tig + 4];
#pragma unroll
            for (int nt = 0; nt < 4; nt++) {
                int n = warpN * 32 + nt * 8 + g;
                uint32_t bh0 = W2h[(k0p + tig)     * STRB + n];
                uint32_t bh1 = W2h[(k0p + tig + 4) * STRB + n];
                uint32_t bl0 = W2l[(k0p + tig)     * STRB + n];
                uint32_t bl1 = W2l[(k0p + tig + 4) * STRB + n];
                mma_bf16(acc2[nt], ah, bh0, bh1);
                mma_bf16(acc2[nt], al, bh0, bh1);
                mma_bf16(acc2[nt], ah, bl0, bl1);
            }
        }
        __syncthreads();   // C1 reads done -> safe to overwrite with C2

        // epilogue2: C2 (fp32 [64][65]) aliases Ah region
        float* bufC = (float*)Ah;
#pragma unroll
        for (int nt = 0; nt < 4; nt++) {
            int n = warpN * 32 + nt * 8 + 2 * tig;
            float bb0 = __ldg(b2 + n), bb1 = __ldg(b2 + n + 1);
            bufC[ row0      * 65 + n    ] = fmaxf(acc2[nt][0] + bb0, 0.f);
            bufC[ row0      * 65 + n + 1] = fmaxf(acc2[nt][1] + bb1, 0.f);
            bufC[(row0 + 8) * 65 + n    ] = fmaxf(acc2[nt][2] + bb0, 0.f);
            bufC[(row0 + 8) * 65 + n + 1] = fmaxf(acc2[nt][3] + bb1, 0.f);
        }
        __syncthreads();

        // GEMM3: [64,64] @ [64,6] -> out
        for (int w = tid; w < 384; w += 256) {
            int e = w & 63, j = w >> 6;
            float s = b3s[j];
#pragma unroll 8
            for (int k = 0; k < 64; k++) s += bufC[e * 65 + k] * W3s[k * 6 + j];
            out[(ebase + e) * 6 + j] = s;
        }
        __syncthreads();   // C2 reads + pad intact before next staging reuses this buffer
        // restore K-pad zeros of this buffer (C1 writes covered kp 0..63 only; pads
        // were untouched by C1; C2 (fp32, 65*64=4160 words < EAB) overlapped pads of
        // early rows -> re-zero pads of Ah half it occupied.
        for (int i = tid; i < ET * 8; i += 256) {
            int e = i >> 3, j = i & 7;
            Ah[e * STRA + 68 + j] = 0;
            Al[e * STRA + 68 + j] = 0;
        }
        __syncthreads();
        cur ^= 1;
    }
}

// ---------------------------------------------------------------------------

extern "C" void kernel_launch(void* const* d_in, const int* in_sizes, int n_in,
                              void* d_out, int out_size) {
    const float* x     = (const float*)d_in[0];
    const int*   ei    = (const int*)d_in[1];
    const float* ea    = (const float*)d_in[2];
    const float* W_enc = (const float*)d_in[3];
    const float* b_enc = (const float*)d_in[4];
    const float* W_msg = (const float*)d_in[5];
    const float* b_msg = (const float*)d_in[6];
    const float* W_upd = (const float*)d_in[7];
    const float* b_upd = (const float*)d_in[8];
    const float* W_nd1 = (const float*)d_in[9];
    const float* b_nd1 = (const float*)d_in[10];
    const float* W_nd2 = (const float*)d_in[11];
    const float* b_nd2 = (const float*)d_in[12];
    const float* W_ed1 = (const float*)d_in[13];
    const float* b_ed1 = (const float*)d_in[14];
    const float* W_ed2 = (const float*)d_in[15];
    const float* b_ed2 = (const float*)d_in[16];
    const float* W_ed3 = (const float*)d_in[17];
    const float* b_ed3 = (const float*)d_in[18];
    float* out = (float*)d_out;

    cudaFuncSetAttribute(msg_kernel, cudaFuncAttributeMaxDynamicSharedMemorySize, MSG_SMEM);
    cudaFuncSetAttribute(upd_kernel, cudaFuncAttributeMaxDynamicSharedMemorySize, UPD_SMEM);
    cudaFuncSetAttribute(edgehead_kernel, cudaFuncAttributeMaxDynamicSharedMemorySize, EH_SMEM);

    split_all_kernel<<<(SPLIT_TOTAL + 255) / 256, 256>>>(W_msg, W_upd, W_ed1, W_ed2);
    split_ea_kernel<<<(EE * 4 + 255) / 256, 256>>>(ea);
    enc_kernel<<<(NN + 255) / 256, 256>>>(x, W_enc, b_enc);
    for (int l = 0; l < 3; l++) {
        zero_agg_kernel<<<(NN * H + 255) / 256, 256>>>();
        msg_kernel<<<GRID_P, 256, MSG_SMEM>>>(ei, b_msg);
        upd_kernel<<<(NN + 63) / 64, 256, UPD_SMEM>>>(b_upd);
    }
    nodehead_kernel<<<(NN + 63) / 64, 256>>>(W_nd1, b_nd1, W_nd2, b_nd2, out);
    edgehead_kernel<<<GRID_P, 256, EH_SMEM>>>(ei, b_ed1, b_ed2, W_ed3, b_ed3,
                                              out + 2 * NN);
}